// round 1
// baseline (speedup 1.0000x reference)
#include <cuda_runtime.h>
#include <math.h>

#define NMODES      6400
#define CHUNK       512          // samples per warp-chunk = 32 lanes * U
#define U           16           // accumulators per lane
#define G           32           // mode groups (partial buffers)
#define MPG         (NMODES / G) // modes per group = 200
#define MAX_SAMPLES 132096
#define MAX_CHUNKS  ((MAX_SAMPLES + CHUNK - 1) / CHUNK)   // 258

// Static scratch (no runtime allocation allowed)
__device__ float4       g_params[NMODES * 2];                 // per-mode constants
__device__ float2       g_init[MAX_CHUNKS * NMODES];          // per (chunk,mode): {amp, phase}
__device__ float        g_partial[(size_t)G * MAX_SAMPLES];   // per-group partial sums
__device__ unsigned int g_maxbits;

__device__ __forceinline__ float softplusf(float x) {
    return (x > 20.f) ? x : log1pf(expf(x));
}

// ---------------------------------------------------------------------------
// Kernel A: per-mode parameters + per-(mode,chunk) exact init table.
// One thread per mode. Phase accumulated in double => exact n*theta mod 2pi.
// ---------------------------------------------------------------------------
__global__ void precompute_kernel(const float* mu_raw, const float* D_raw,
                                  const float* T0_raw, const float* Ly_raw,
                                  const float* xo_raw, const float* yo_raw,
                                  int nchunks)
{
    int m = blockIdx.x * blockDim.x + threadIdx.x;
    if (m >= NMODES) return;
    if (m == 0) g_maxbits = 0u;    // reset peak for this replay

    const float  PI    = 3.14159265358979323846f;
    const float  LX    = 0.5f;
    const float  Kf    = 1.0f / 44100.0f;
    const float  MAXOM = (float)(20000.0 * M_PI);
    const float  MINOM = (float)(40.0 * M_PI);
    const double OM2   = 2.0 * M_PI * 500.0;
    const double DOMSQ = OM2 * OM2;
    const double L10_3 = 3.0 * 2.302585092994045684;   // 3*ln(10)
    const float  ALPHA = (float)(L10_3 / DOMSQ * (DOMSQ / 6.0));
    const float  BETA  = (float)(L10_3 / DOMSQ * (1.0 - 1.0 / 6.0));

    float mu = softplusf(mu_raw[0]) + 1e-4f;
    float Dm = softplusf(D_raw[0])  + 1e-4f;
    float T0 = softplusf(T0_raw[0]) + 1e-4f;
    float Ly = 1.1f + (4.0f - 1.1f) * ((tanhf(Ly_raw[0]) + 1.0f) * 0.5f);
    float xo = 0.49f * LX + (1.0f - 0.49f) * LX * ((tanhf(xo_raw[0]) + 1.0f) * 0.5f);
    float yo = 0.51f * Ly + (1.0f - 0.51f) * Ly * ((tanhf(yo_raw[0]) + 1.0f) * 0.5f);
    float xi = 0.1f * LX;
    float yi = 0.1f * Ly;

    float Mf = (float)(m / 80 + 1);
    float Nf = (float)(m % 80 + 1);

    float a1 = Mf * PI / LX;
    float a2 = Nf * PI / Ly;
    float g1 = a1 * a1 + a2 * a2;
    float om2 = T0 * g1 + Dm * g1 * g1;
    float omega = sqrtf(fmaxf(om2, 0.f));
    bool valid = (omega <= MAXOM) && (omega >= MINOM);

    float in_w  = cosf(xi * PI * Mf / LX) * cosf(yi * PI * Nf / Ly);
    float out_w = cosf(xo * PI * Mf / LX) * cosf(yo * PI * Nf / Ly);
    float sigma = ALPHA + BETA * omega * omega;
    float msf   = 0.25f * mu * LX * Ly;
    float theta = omega * Kf;
    float denom = sinf(theta) + 1e-8f;

    // Signal per mode: s[n] = C * r^n * sin(n*theta), r = exp(-sigma*K)
    // matches ref: P * r^(n-1) * sin(n*theta)/denom with P containing one r.
    double thd = (double)theta;
    double sKd = (double)sigma * (1.0 / 44100.0);
    double Cd  = 0.0;
    float c1f = 0.f, c2f = 0.f, rinv32f = 0.f, cs32f = 0.f, sn32f = 0.f;
    if (valid) {
        Cd = (double)out_w * (double)in_w * ((double)Kf * (double)Kf)
             / ((double)msf * (double)denom);
        double r32 = exp(-32.0 * sKd);
        double c32 = cos(32.0 * thd);
        double s32 = sin(32.0 * thd);
        c1f     = (float)(2.0 * r32 * c32);
        c2f     = (float)(r32 * r32);
        rinv32f = (float)(1.0 / r32);
        cs32f   = (float)c32;
        sn32f   = (float)s32;
    }
    g_params[2 * m]     = make_float4(theta, (float)(-sKd), c1f, c2f);
    g_params[2 * m + 1] = make_float4(rinv32f, cs32f, sn32f, 0.f);

    const double TWO_PI = 6.283185307179586476925;
    double dphi = fmod((double)CHUNK * thd, TWO_PI);
    double rc   = exp(-(double)CHUNK * sKd);
    double amp  = Cd;
    double phi  = 0.0;
    double thresh = fabs(Cd) * 1e-20;    // below this the mode is inaudible -> skip flag
    for (int c = 0; c < nchunks; c++) {
        float a0 = (fabs(amp) > thresh) ? (float)amp : 0.0f;
        g_init[(size_t)c * NMODES + m] = make_float2(a0, (float)phi);
        amp *= rc;
        phi += dphi;
        if (phi >= TWO_PI) phi -= TWO_PI;
    }
}

// ---------------------------------------------------------------------------
// Kernel B: main synthesis. One warp = (time-chunk c, mode-group g).
// Lane l carries samples n0+l, n0+l+32, ... via a stride-32 recurrence:
//   u[n+32] = 2 r^32 cos(32th) u[n] - r^64 u[n-32]
// initialized exactly per mode from the phase table.
// ---------------------------------------------------------------------------
__global__ void __launch_bounds__(256) modal_kernel(int N, int nchunks)
{
    int gwarp = (int)((blockIdx.x * blockDim.x + threadIdx.x) >> 5);
    int lane  = threadIdx.x & 31;
    int total = nchunks * G;
    if (gwarp >= total) return;
    int c = gwarp % nchunks;
    int g = gwarp / nchunks;
    int n0 = c * CHUNK;

    float acc[U];
#pragma unroll
    for (int j = 0; j < U; j++) acc[j] = 0.f;

    float lf = (float)lane;
    const float2* init_c = g_init + (size_t)c * NMODES;

    for (int k = 0; k < MPG; k++) {
        int m = g + k * G;                 // interleaved modes -> balanced groups
        float2 ini = init_c[m];
        float A0 = ini.x;
        if (A0 == 0.0f) continue;          // decayed or invalid (warp-uniform)
        float4 pa = g_params[2 * m];
        float4 pb = g_params[2 * m + 1];
        float theta = pa.x, msigK = pa.y, c1 = pa.z, c2 = pa.w;
        float rinv32 = pb.x, cs32 = pb.y, sn32 = pb.z;

        float a = fmaf(lf, theta, ini.y);
        a -= 6.2831855f * rintf(a * 0.15915494f);   // reduce to [-pi, pi]
        float s, co;
        __sincosf(a, &s, &co);
        float el = __expf(msigK * lf);
        float Ae = A0 * el;
        float cur  = Ae * s;                                    // s[n0+lane]
        float prev = Ae * rinv32 * fmaf(s, cs32, -co * sn32);   // s[n0+lane-32]
#pragma unroll
        for (int j = 0; j < U; j++) {
            acc[j] += cur;
            float t   = c2 * prev;
            float nxt = fmaf(c1, cur, -t);
            prev = cur;
            cur  = nxt;
        }
    }

    float* dst = g_partial + (size_t)g * MAX_SAMPLES + n0 + lane;
#pragma unroll
    for (int j = 0; j < U; j++) {
        int n = n0 + 32 * j + lane;
        if (n < N) dst[32 * j] = acc[j];
    }
}

// ---------------------------------------------------------------------------
// Kernel C: sum the G partial buffers, write unnormalized output, track peak.
// ---------------------------------------------------------------------------
__global__ void reduce_kernel(float* out, int N)
{
    int n = blockIdx.x * blockDim.x + threadIdx.x;
    float v = 0.f;
    if (n < N) {
#pragma unroll
        for (int g = 0; g < G; g++)
            v += g_partial[(size_t)g * MAX_SAMPLES + n];
        out[n] = v;
    }
    float am = (n < N) ? fabsf(v) : 0.f;
#pragma unroll
    for (int o = 16; o; o >>= 1)
        am = fmaxf(am, __shfl_xor_sync(0xffffffffu, am, o));
    __shared__ float wmax[8];
    int w = threadIdx.x >> 5;
    if ((threadIdx.x & 31) == 0) wmax[w] = am;
    __syncthreads();
    if (threadIdx.x == 0) {
        float bm = wmax[0];
        int nw = blockDim.x >> 5;
        for (int i = 1; i < nw; i++) bm = fmaxf(bm, wmax[i]);
        atomicMax(&g_maxbits, __float_as_uint(bm));   // abs vals >= 0: int-monotonic
    }
}

__global__ void norm_kernel(float* out, int N)
{
    int n = blockIdx.x * blockDim.x + threadIdx.x;
    if (n < N) {
        float peak = __uint_as_float(g_maxbits) + 1e-8f;
        out[n] = out[n] / peak;
    }
}

// ---------------------------------------------------------------------------
extern "C" void kernel_launch(void* const* d_in, const int* in_sizes, int n_in,
                              void* d_out, int out_size)
{
    const float* mu_raw = (const float*)d_in[0];
    const float* D_raw  = (const float*)d_in[1];
    const float* T0_raw = (const float*)d_in[2];
    const float* Ly_raw = (const float*)d_in[3];
    const float* xo_raw = (const float*)d_in[4];
    const float* yo_raw = (const float*)d_in[5];
    // d_in[6] = num_samples (device scalar); out_size carries the same value host-side.

    int N = out_size;
    if (N > MAX_SAMPLES) N = MAX_SAMPLES;
    int nchunks = (N + CHUNK - 1) / CHUNK;

    precompute_kernel<<<(NMODES + 255) / 256, 256>>>(mu_raw, D_raw, T0_raw,
                                                     Ly_raw, xo_raw, yo_raw, nchunks);

    int total_warps = nchunks * G;
    int blocks = (total_warps * 32 + 255) / 256;
    modal_kernel<<<blocks, 256>>>(N, nchunks);

    int rb = (N + 255) / 256;
    reduce_kernel<<<rb, 256>>>((float*)d_out, N);
    norm_kernel<<<rb, 256>>>((float*)d_out, N);
}

// round 2
// speedup vs baseline: 1.9237x; 1.9237x over previous
#include <cuda_runtime.h>
#include <math.h>

#define NMODES      6400
#define NB          25            // blocks of 256 over modes
#define NBINS       260           // lifetime bins (0..258)
#define CHUNK       512           // samples per warp-chunk = 32 lanes * U
#define U           16            // accumulators per lane
#define G           32            // mode groups (partial buffers)
#define MAX_SAMPLES 132096
#define MAX_CHUNKS  258
#define TLN         23.0f         // -ln(1e-10) relative amplitude cutoff

// Static scratch (no runtime allocation allowed)
__device__ float4       g_uA[NMODES], g_uB[NMODES];   // unsorted per-mode params
__device__ int          g_Lm[NMODES];                 // lifetime in chunks
__device__ int          g_hist2[NBINS][NB];
__device__ int          g_off2[NBINS][NB];
__device__ int          g_cnt[MAX_CHUNKS];            // #active modes at chunk c
__device__ float4       g_pA[NMODES], g_pB[NMODES];   // lifetime-sorted params
__device__ float        g_partial[(size_t)G * MAX_SAMPLES];
__device__ unsigned int g_maxbits;

__device__ __forceinline__ float softplusf(float x) {
    return (x > 20.f) ? x : log1pf(expf(x));
}

// ---------------------------------------------------------------------------
// P1: per-mode params, lifetime, per-block lifetime histogram. 25 x 256.
// ---------------------------------------------------------------------------
__global__ void p1_kernel(const float* mu_raw, const float* D_raw,
                          const float* T0_raw, const float* Ly_raw,
                          const float* xo_raw, const float* yo_raw,
                          int nchunks)
{
    __shared__ int sh_hist[NBINS];
    int tid = threadIdx.x, b = blockIdx.x;
    for (int i = tid; i < NBINS; i += 256) sh_hist[i] = 0;
    if (b == 0 && tid == 0) g_maxbits = 0u;
    __syncthreads();

    int m = b * 256 + tid;

    const float  PI    = 3.14159265358979323846f;
    const float  LX    = 0.5f;
    const float  Kf    = 1.0f / 44100.0f;
    const float  MAXOM = (float)(20000.0 * M_PI);
    const float  MINOM = (float)(40.0 * M_PI);
    const double OM2   = 2.0 * M_PI * 500.0;
    const double DOMSQ = OM2 * OM2;
    const double L10_3 = 3.0 * 2.302585092994045684;   // 3*ln(10)
    const float  ALPHA = (float)(L10_3 / DOMSQ * (DOMSQ / 6.0));
    const float  BETA  = (float)(L10_3 / DOMSQ * (1.0 - 1.0 / 6.0));

    float mu = softplusf(mu_raw[0]) + 1e-4f;
    float Dm = softplusf(D_raw[0])  + 1e-4f;
    float T0 = softplusf(T0_raw[0]) + 1e-4f;
    float Ly = 1.1f + (4.0f - 1.1f) * ((tanhf(Ly_raw[0]) + 1.0f) * 0.5f);
    float xo = 0.49f * LX + (1.0f - 0.49f) * LX * ((tanhf(xo_raw[0]) + 1.0f) * 0.5f);
    float yo = 0.51f * Ly + (1.0f - 0.51f) * Ly * ((tanhf(yo_raw[0]) + 1.0f) * 0.5f);
    float xi = 0.1f * LX;
    float yi = 0.1f * Ly;

    float Mf = (float)(m / 80 + 1);
    float Nf = (float)(m % 80 + 1);

    float a1 = Mf * PI / LX;
    float a2 = Nf * PI / Ly;
    float g1 = a1 * a1 + a2 * a2;
    float om2 = T0 * g1 + Dm * g1 * g1;
    float omega = sqrtf(fmaxf(om2, 0.f));
    bool valid = (omega <= MAXOM) && (omega >= MINOM);

    float in_w  = cosf(xi * PI * Mf / LX) * cosf(yi * PI * Nf / Ly);
    float out_w = cosf(xo * PI * Mf / LX) * cosf(yo * PI * Nf / Ly);
    float sigma = ALPHA + BETA * omega * omega;
    float msf   = 0.25f * mu * LX * Ly;
    float theta = omega * Kf;
    float denom = sinf(theta) + 1e-8f;
    float sigK  = sigma * Kf;

    // s[n] = C * r^n * sin(n*theta), r = exp(-sigma*K)
    float Cf = out_w * in_w * (Kf * Kf) / (msf * denom);

    int L = 0;
    float c1f = 0.f, c2f = 0.f, rinv32f = 0.f, cs32f = 0.f, sn32f = 0.f;
    if (valid) {
        double thd = (double)theta;
        double sKd = (double)sigK;
        double r32 = exp(-32.0 * sKd);
        double c32 = cos(32.0 * thd);
        double s32 = sin(32.0 * thd);
        c1f     = (float)(2.0 * r32 * c32);
        c2f     = (float)(r32 * r32);
        rinv32f = (float)(1.0 / r32);
        cs32f   = (float)c32;
        sn32f   = (float)s32;
        // lifetime in chunks: active while n*sigK < TLN
        float lc = TLN / (sigK * (float)CHUNK);
        int   Li = (lc >= (float)nchunks) ? nchunks : ((int)lc + 1);
        L = (Li > nchunks) ? nchunks : Li;
        if (L < 1) L = 1;
    }

    g_uA[m] = make_float4(theta, -sigK, c1f, c2f);
    g_uB[m] = make_float4(rinv32f, cs32f, sn32f, valid ? Cf : 0.f);
    g_Lm[m] = L;
    atomicAdd(&sh_hist[L], 1);
    __syncthreads();
    for (int i = tid; i < NBINS; i += 256) g_hist2[i][b] = sh_hist[i];
}

// ---------------------------------------------------------------------------
// P2: prefix sums over (lifetime, block) histogram. 1 block x 256.
// Sort order: descending lifetime, ascending block, original order in block.
// ---------------------------------------------------------------------------
__global__ void p2_kernel(int nchunks)
{
    __shared__ int histL[NBINS];
    __shared__ int offL[NBINS];
    int tid = threadIdx.x;
    for (int i = tid; i < NBINS; i += 256) {
        int s = 0;
#pragma unroll
        for (int b = 0; b < NB; b++) s += g_hist2[i][b];
        histL[i] = s;
    }
    __syncthreads();
    if (tid == 0) {
        int run = 0;
        for (int L = NBINS - 1; L >= 0; --L) { offL[L] = run; run += histL[L]; }
    }
    __syncthreads();
    for (int c = tid; c < nchunks; c += 256) g_cnt[c] = offL[c];
    for (int i = tid; i < NBINS; i += 256) {
        int run = offL[i];
        int h[NB];
#pragma unroll
        for (int b = 0; b < NB; b++) h[b] = g_hist2[i][b];
#pragma unroll
        for (int b = 0; b < NB; b++) { g_off2[i][b] = run; run += h[b]; }
    }
}

// ---------------------------------------------------------------------------
// P3: deterministic scatter into lifetime-sorted arrays. 25 x 256.
// ---------------------------------------------------------------------------
__global__ void p3_kernel()
{
    __shared__ int shL[256];
    int tid = threadIdx.x, b = blockIdx.x;
    int m = b * 256 + tid;
    int L = g_Lm[m];
    shL[tid] = L;
    __syncthreads();
    int local = 0;
    for (int i = 0; i < tid; i++) local += (shL[i] == L);
    int rank = g_off2[L][b] + local;
    g_pA[rank] = g_uA[m];
    g_pB[rank] = g_uB[m];
}

// ---------------------------------------------------------------------------
// Modal synthesis. One warp = (chunk c, group g); contiguous rank range,
// branch-free. Lane l carries samples n0+l, n0+l+32, ... via stride-32
// recurrence u[n+32] = c1 u[n] - c2 u[n-32], initialized exactly per mode
// with a float Cody-Waite phase reduction (no fp64 in hot path).
// ---------------------------------------------------------------------------
__global__ void __launch_bounds__(256) modal_kernel(int N, int nchunks)
{
    const float INV2PI = 0.15915494309189535f;
    const float P2_0 = 6.28125f;
    const float P2_1 = (float)(6.283185307179586476925 - 6.28125);
    const float P2_2 = (float)(6.283185307179586476925 - 6.28125
                               - (double)(float)(6.283185307179586476925 - 6.28125));

    int w    = (int)((blockIdx.x * blockDim.x + threadIdx.x) >> 5);
    int lane = threadIdx.x & 31;
    int total = nchunks * G;
    if (w >= total) return;
    int c = w % nchunks;
    int g = w / nchunks;
    int n0 = c * CHUNK;

    int cnt  = g_cnt[c];
    int base = (cnt * g) >> 5;          // G == 32
    int end  = (cnt * (g + 1)) >> 5;

    float acc[U];
#pragma unroll
    for (int j = 0; j < U; j++) acc[j] = 0.f;

    float lf  = (float)lane;
    float n0f = (float)n0;

#pragma unroll 2
    for (int r = base; r < end; ++r) {
        float4 pa = g_pA[r];
        float4 pb = g_pB[r];
        float theta = pa.x, msigK = pa.y, c1 = pa.z, c2 = pa.w;
        float rinv32 = pb.x, cs32 = pb.y, sn32 = pb.z, C = pb.w;

        // chunk phase: (n0 * theta) mod 2pi, exact product + 3-term reduction
        float p  = n0f * theta;
        float e  = fmaf(n0f, theta, -p);
        float k  = rintf(p * INV2PI);
        float rr = fmaf(-k, P2_0, p);
        rr = fmaf(-k, P2_1, rr);
        rr = fmaf(-k, P2_2, rr);
        float psi = rr + e;

        // per-lane phase and amplitude
        float a  = fmaf(lf, theta, psi);
        float k2 = rintf(a * INV2PI);
        a = fmaf(-k2, P2_0, a);
        a = fmaf(-k2, P2_1, a);
        float s, co;
        __sincosf(a, &s, &co);
        float Ae  = C * __expf(msigK * (n0f + lf));
        float cur  = Ae * s;                                    // s[n0+lane]
        float prev = (Ae * rinv32) * fmaf(s, cs32, -co * sn32); // s[n0+lane-32]
#pragma unroll
        for (int j = 0; j < U; j++) {
            acc[j] += cur;
            float t   = c2 * prev;
            float nxt = fmaf(c1, cur, -t);
            prev = cur;
            cur  = nxt;
        }
    }

    float* dst = g_partial + (size_t)g * MAX_SAMPLES + n0 + lane;
#pragma unroll
    for (int j = 0; j < U; j++) {
        int n = n0 + 32 * j + lane;
        if (n < N) dst[32 * j] = acc[j];
    }
}

// ---------------------------------------------------------------------------
// Sum the G partial buffers, write unnormalized output, track peak.
// ---------------------------------------------------------------------------
__global__ void reduce_kernel(float* out, int N)
{
    int n = blockIdx.x * blockDim.x + threadIdx.x;
    float v = 0.f;
    if (n < N) {
#pragma unroll
        for (int g = 0; g < G; g++)
            v += g_partial[(size_t)g * MAX_SAMPLES + n];
        out[n] = v;
    }
    float am = (n < N) ? fabsf(v) : 0.f;
#pragma unroll
    for (int o = 16; o; o >>= 1)
        am = fmaxf(am, __shfl_xor_sync(0xffffffffu, am, o));
    __shared__ float wmax[8];
    int wr = threadIdx.x >> 5;
    if ((threadIdx.x & 31) == 0) wmax[wr] = am;
    __syncthreads();
    if (threadIdx.x == 0) {
        float bm = wmax[0];
        int nw = blockDim.x >> 5;
        for (int i = 1; i < nw; i++) bm = fmaxf(bm, wmax[i]);
        atomicMax(&g_maxbits, __float_as_uint(bm));   // abs vals >= 0: int-monotonic
    }
}

__global__ void norm_kernel(float* out, int N)
{
    int n = blockIdx.x * blockDim.x + threadIdx.x;
    if (n < N) {
        float peak = __uint_as_float(g_maxbits) + 1e-8f;
        out[n] = out[n] / peak;
    }
}

// ---------------------------------------------------------------------------
extern "C" void kernel_launch(void* const* d_in, const int* in_sizes, int n_in,
                              void* d_out, int out_size)
{
    const float* mu_raw = (const float*)d_in[0];
    const float* D_raw  = (const float*)d_in[1];
    const float* T0_raw = (const float*)d_in[2];
    const float* Ly_raw = (const float*)d_in[3];
    const float* xo_raw = (const float*)d_in[4];
    const float* yo_raw = (const float*)d_in[5];

    int N = out_size;
    if (N > MAX_SAMPLES) N = MAX_SAMPLES;
    int nchunks = (N + CHUNK - 1) / CHUNK;

    p1_kernel<<<NB, 256>>>(mu_raw, D_raw, T0_raw, Ly_raw, xo_raw, yo_raw, nchunks);
    p2_kernel<<<1, 256>>>(nchunks);
    p3_kernel<<<NB, 256>>>();

    int total_warps = nchunks * G;
    int blocks = (total_warps * 32 + 255) / 256;
    modal_kernel<<<blocks, 256>>>(N, nchunks);

    int rb = (N + 255) / 256;
    reduce_kernel<<<rb, 256>>>((float*)d_out, N);
    norm_kernel<<<rb, 256>>>((float*)d_out, N);
}